// round 14
// baseline (speedup 1.0000x reference)
#include <cuda_runtime.h>
#include <math.h>
#include <cstdint>

#define NPART 32768
#define DD 32
#define PP 8
#define HH 128
#define MS 50
#define TPB 512
#define NBLK 128    // NBLK * (TPB/2) == NPART
#define HALF 256

typedef unsigned long long u64;

// W2 weights, j-major [128][32] — read over the constant port (warp-uniform).
__constant__ float W2c[HH * DD];

// ---- packed f32x2 helpers (sm_103a) ----
__device__ __forceinline__ u64 pack2(float lo, float hi) {
    u64 r; asm("mov.b64 %0, {%1, %2};" : "=l"(r) : "f"(lo), "f"(hi)); return r;
}
__device__ __forceinline__ void unpack2(u64 v, float& lo, float& hi) {
    asm("mov.b64 {%0, %1}, %2;" : "=f"(lo), "=f"(hi) : "l"(v));
}
__device__ __forceinline__ u64 fma2(u64 a, u64 b, u64 c) {
    u64 d; asm("fma.rn.f32x2 %0, %1, %2, %3;" : "=l"(d) : "l"(a), "l"(b), "l"(c)); return d;
}
__device__ __forceinline__ u64 add2(u64 a, u64 b) {
    u64 d; asm("add.rn.f32x2 %0, %1, %2;" : "=l"(d) : "l"(a), "l"(b)); return d;
}
__device__ __forceinline__ u64 mul2(u64 a, u64 b) {
    u64 d; asm("mul.rn.f32x2 %0, %1, %2;" : "=l"(d) : "l"(a), "l"(b)); return d;
}
__device__ __forceinline__ uint32_t smem_u32(const void* p) {
    uint32_t a;
    asm("{ .reg .u64 t; cvta.to.shared.u64 t, %1; cvt.u32.u64 %0, t; }"
        : "=r"(a) : "l"(p));
    return a;
}
__device__ __forceinline__ float ftanh(float a) {
    float e = __expf(2.0f * a);
    return 1.0f - __fdividef(2.0f, e + 1.0f);
}
#define CP16(dst, src) \
    asm volatile("cp.async.cg.shared.global [%0], [%1], 16;" \
                 :: "r"(dst), "l"(src) : "memory")

// dynamic shared layout (float offsets)
#define F_W1T 0                       // [j][i] 128x32
#define F_NS  (F_W1T + HH * DD)       // noise: [chunk(8)][pid(256)][4]
#define F_ZX  (F_NS + HALF * DD)      // Z exchange: u64[16][512]
#define SMEM_FLOATS (F_ZX + 16 * TPB * 2)
#define SMEM_BYTES (SMEM_FLOATS * 4)

// layer-1 for unit pair (u, u+32), base pointer W1B = W1T + (h*64)*DD
#define LAYER1(JJ, P0, P1) do { \
    const ulonglong2* _w1a = (const ulonglong2*)(w1base + (JJ) * DD); \
    const ulonglong2* _w1b = (const ulonglong2*)(w1base + ((JJ) + 32) * DD); \
    u64 _q0 = zero2, _q1 = zero2, _q2 = zero2, _q3 = zero2; \
    _Pragma("unroll") \
    for (int _i = 0; _i < 8; _i++) { \
        ulonglong2 _wa = _w1a[_i]; \
        ulonglong2 _wb = _w1b[_i]; \
        _q0 = fma2(Xp[2*_i],   _wa.x, _q0); \
        _q1 = fma2(Xp[2*_i+1], _wa.y, _q1); \
        _q2 = fma2(Xp[2*_i],   _wb.x, _q2); \
        _q3 = fma2(Xp[2*_i+1], _wb.y, _q3); \
    } \
    _q0 = add2(_q0, _q1); \
    _q2 = add2(_q2, _q3); \
    const float2 _cs = csp[JJ]; \
    float _tl, _th; \
    unpack2(_q0, _tl, _th); (P0) = _cs.x + (_tl + _th); \
    unpack2(_q2, _tl, _th); (P1) = _cs.y + (_tl + _th); \
} while (0)

// layer-2 accumulate for unit pair (u, u+32); W2 via const port (warp-uniform)
#define LAYER2(JJ, H0P, H1P) do { \
    const ulonglong2* _w2a = (const ulonglong2*)(w2base + (JJ) * DD); \
    const ulonglong2* _w2b = (const ulonglong2*)(w2base + ((JJ) + 32) * DD); \
    _Pragma("unroll") \
    for (int _i = 0; _i < 8; _i++) { \
        ulonglong2 _wa = _w2a[_i]; \
        ulonglong2 _wb = _w2b[_i]; \
        Zp[2*_i]   = fma2((H0P), _wa.x, Zp[2*_i]); \
        Zp[2*_i+1] = fma2((H0P), _wa.y, Zp[2*_i+1]); \
        Zp[2*_i]   = fma2((H1P), _wb.x, Zp[2*_i]); \
        Zp[2*_i+1] = fma2((H1P), _wb.y, Zp[2*_i+1]); \
    } \
} while (0)

__global__ __launch_bounds__(TPB, 1)
void sde_kernel(const float* __restrict__ obs,
                const float* __restrict__ X0,
                const float* __restrict__ V0,
                const float* __restrict__ noise,
                const float* __restrict__ W1,
                const float* __restrict__ b1,
                const float* __restrict__ b2,
                const float* __restrict__ theta_p,
                const int*   __restrict__ obsidx_p,
                const int*   __restrict__ cr_p,
                float* __restrict__ outX,
                float* __restrict__ outV)
{
    extern __shared__ __align__(16) float sm[];
    float* W1T = sm + F_W1T;
    float* ns  = sm + F_NS;
    u64*   zx  = (u64*)(sm + F_ZX);

    __shared__ float2 cb[HH];           // (base_j, w40_j)
    __shared__ float2 cspbuf[2][HH/2];  // cs pairs (u, u+32), double-buffered
    __shared__ __align__(16) float b2s[DD];

    const int tid = threadIdx.x;
    const int h   = tid >> 8;           // which hidden-unit half this thread owns
    const int lt  = tid & (HALF - 1);   // particle slot within CTA

    // ---- stage W1^T + folded constants ----
    for (int idx = tid; idx < DD * HH; idx += TPB) {
        int i = idx >> 7;
        int j = idx & (HH - 1);
        W1T[j * DD + i] = W1[idx];
    }
    if (tid < DD) b2s[tid] = b2[tid];
    if (tid < HH) {
        const int j = tid;
        float base = b1[j];
        #pragma unroll
        for (int q = 0; q < PP; q++)
            base = fmaf(obs[q], W1[(DD + q) * HH + j], base);
        base = fmaf((float)(*obsidx_p), W1[41 * HH + j], base);
        cb[j] = make_float2(base, W1[40 * HH + j]);
    }

    const float theta = *theta_p;
    const float crf   = (float)(*cr_p);
    const float dt    = 0.02f;
    const float sqdt  = sqrtf(dt);

    const u64 sq2   = pack2(sqdt, sqdt);
    const u64 dt2   = pack2(dt, dt);
    const u64 nth2  = pack2(-theta, -theta);
    const u64 ncr2  = pack2(-crf, -crf);
    const u64 zero2 = pack2(0.f, 0.f);

    const int p = (int)blockIdx.x * HALF + lt;   // particle id

    const uint32_t nsu = smem_u32(ns) + (uint32_t)lt * 16u;
    const float* nrd = ns + lt * 4;
    const float* w1base = W1T + (h * 64) * DD;
    const float* w2base = W2c + (h * 64) * DD;

    __syncthreads();

    // ---- full X state per thread; partial Z per thread ----
    u64 Xp[DD/2], Zp[DD/2];
    {
        const ulonglong2* xr = (const ulonglong2*)(X0 + (size_t)p * DD);
        #pragma unroll
        for (int i = 0; i < DD/4; i++) {
            ulonglong2 v = xr[i];
            Xp[2*i] = v.x; Xp[2*i+1] = v.y;
        }
    }
    float V = V0[p];

    const u64* b2u = (const u64*)b2s;

    for (int m = 0; m < MS; m++) {
        const float s = (float)m * dt;

        // per-step cs pairs for unit pair (u, u+32); double-buffered
        if (tid < HH / 2) {
            const int hh = tid >> 5, jj = tid & 31;
            const int u0 = hh * 64 + jj;
            float2 ca = cb[u0];
            float2 cbx = cb[u0 + 32];
            cspbuf[m & 1][tid] =
                make_float2(fmaf(s, ca.y, ca.x), fmaf(s, cbx.y, cbx.x));
        }
        // stage this step's noise (once per particle; h==0 warps produce)
        if (h == 0) {
            const float* src = noise + ((size_t)m * NPART + p) * DD;
            #pragma unroll
            for (int i = 0; i < 8; i++)
                CP16(nsu + (uint32_t)i * (HALF * 16u), src + i * 4);
            asm volatile("cp.async.commit_group;" ::: "memory");
        }
        __syncthreads();   // csp ready; zx buffer free for this step

        const float2* csp = cspbuf[m & 1] + (h << 5);

        // partial Z: h==0 carries b2, h==1 starts at zero
        #pragma unroll
        for (int i = 0; i < DD/2; i++) Zp[i] = (h == 0) ? b2u[i] : zero2;

        // ---- software-pipelined half-MLP (32 unit pairs) ----
        float pre0, pre1;
        LAYER1(0, pre0, pre1);
        #pragma unroll 2
        for (int jj = 0; jj < HH / 4 - 1; jj++) {
            const float h0 = ftanh(pre0);
            const float h1 = ftanh(pre1);
            float npre0, npre1;
            LAYER1(jj + 1, npre0, npre1);
            const u64 h0p = pack2(h0, h0);
            const u64 h1p = pack2(h1, h1);
            LAYER2(jj, h0p, h1p);
            pre0 = npre0;
            pre1 = npre1;
        }
        {
            const float h0 = ftanh(pre0);
            const float h1 = ftanh(pre1);
            const u64 h0p = pack2(h0, h0);
            const u64 h1p = pack2(h1, h1);
            LAYER2(HH / 4 - 1, h0p, h1p);
        }

        // ---- exchange partial Z with pair thread ----
        #pragma unroll
        for (int i = 0; i < DD/2; i++) zx[i * TPB + tid] = Zp[i];
        if (h == 0)
            asm volatile("cp.async.wait_group 0;" ::: "memory");
        __syncthreads();
        {
            const int pt = tid ^ HALF;
            #pragma unroll
            for (int i = 0; i < DD/2; i++)
                Zp[i] = add2(Zp[i], zx[i * TPB + pt]);
        }

        // ---- epilogue (full Z; duplicated across the pair, bit-identical) ----
        u64 s20 = zero2, s21 = zero2, s22 = zero2, s23 = zero2;
        u64 zw0 = zero2, zw1 = zero2, zw2 = zero2, zw3 = zero2;
        #pragma unroll
        for (int i = 0; i < 4; i++) {
            ulonglong2 nv0 = *(const ulonglong2*)(nrd + (2*i)     * (HALF * 4));
            ulonglong2 nv1 = *(const ulonglong2*)(nrd + (2*i + 1) * (HALF * 4));
            u64 za = Zp[4*i],     zb = Zp[4*i + 1];
            u64 zc = Zp[4*i + 2], zd = Zp[4*i + 3];
            s20 = fma2(za, za, s20);
            s21 = fma2(zb, zb, s21);
            s22 = fma2(zc, zc, s22);
            s23 = fma2(zd, zd, s23);
            u64 wa = mul2(sq2, nv0.x);
            u64 wb = mul2(sq2, nv0.y);
            u64 wc = mul2(sq2, nv1.x);
            u64 wd = mul2(sq2, nv1.y);
            zw0 = fma2(za, wa, zw0);
            zw1 = fma2(zb, wb, zw1);
            zw2 = fma2(zc, wc, zw2);
            zw3 = fma2(zd, wd, zw3);
            u64 d0 = fma2(ncr2, za, mul2(nth2, Xp[4*i]));
            u64 d1 = fma2(ncr2, zb, mul2(nth2, Xp[4*i + 1]));
            u64 d2 = fma2(ncr2, zc, mul2(nth2, Xp[4*i + 2]));
            u64 d3 = fma2(ncr2, zd, mul2(nth2, Xp[4*i + 3]));
            Xp[4*i]     = add2(fma2(dt2, d0, Xp[4*i]),     wa);
            Xp[4*i + 1] = add2(fma2(dt2, d1, Xp[4*i + 1]), wb);
            Xp[4*i + 2] = add2(fma2(dt2, d2, Xp[4*i + 2]), wc);
            Xp[4*i + 3] = add2(fma2(dt2, d3, Xp[4*i + 3]), wd);
        }
        s20 = add2(add2(s20, s21), add2(s22, s23));
        zw0 = add2(add2(zw0, zw1), add2(zw2, zw3));
        float qlo, qhi, wlo, whi;
        unpack2(s20, qlo, qhi);
        unpack2(zw0, wlo, whi);
        V = fmaf(dt * (0.5f - crf), qlo + qhi, V) + (wlo + whi);
    }

    // ---- store (h==0 thread of each pair) ----
    if (h == 0) {
        ulonglong2* xo = (ulonglong2*)(outX + (size_t)p * DD);
        #pragma unroll
        for (int i = 0; i < DD/4; i++) {
            ulonglong2 v; v.x = Xp[2*i]; v.y = Xp[2*i+1];
            xo[i] = v;
        }
        outV[p] = V;
    }
}

extern "C" void kernel_launch(void* const* d_in, const int* in_sizes, int n_in,
                              void* d_out, int out_size) {
    const float* obs    = (const float*)d_in[0];
    const float* X0     = (const float*)d_in[1];
    const float* V0     = (const float*)d_in[2];
    const float* noise  = (const float*)d_in[3];
    const float* W1     = (const float*)d_in[4];
    const float* b1     = (const float*)d_in[5];
    const float* W2     = (const float*)d_in[6];
    const float* b2     = (const float*)d_in[7];
    const float* theta  = (const float*)d_in[8];
    const int*   obsidx = (const int*)d_in[9];
    const int*   cr     = (const int*)d_in[10];

    float* out  = (float*)d_out;
    float* outX = out;
    float* outV = out + (size_t)NPART * DD;

    // Stage W2 into constant memory (D2D async copy: graph-capturable, no alloc)
    cudaMemcpyToSymbolAsync(W2c, W2, HH * DD * sizeof(float), 0,
                            cudaMemcpyDeviceToDevice, 0);

    cudaFuncSetAttribute(sde_kernel,
                         cudaFuncAttributeMaxDynamicSharedMemorySize, SMEM_BYTES);
    sde_kernel<<<NBLK, TPB, SMEM_BYTES>>>(obs, X0, V0, noise, W1, b1, b2,
                                          theta, obsidx, cr, outX, outV);
}

// round 15
// speedup vs baseline: 1.3396x; 1.3396x over previous
#include <cuda_runtime.h>
#include <math.h>
#include <cstdint>

#define NPART 32768
#define DD 32
#define PP 8
#define HH 128
#define MS 50
#define TPB 256
#define NBLK 128   // TPB*NBLK == NPART exactly

typedef unsigned long long u64;

// W2 weights, j-major [128][32]. Only rows 64..127 are read from here
// (rows 0..63 go through shared) — halves the LDC->LDC floor-8 serialization.
__constant__ float W2c[HH * DD];

// ---- packed f32x2 helpers (sm_103a) ----
__device__ __forceinline__ u64 pack2(float lo, float hi) {
    u64 r; asm("mov.b64 %0, {%1, %2};" : "=l"(r) : "f"(lo), "f"(hi)); return r;
}
__device__ __forceinline__ void unpack2(u64 v, float& lo, float& hi) {
    asm("mov.b64 {%0, %1}, %2;" : "=f"(lo), "=f"(hi) : "l"(v));
}
__device__ __forceinline__ u64 fma2(u64 a, u64 b, u64 c) {
    u64 d; asm("fma.rn.f32x2 %0, %1, %2, %3;" : "=l"(d) : "l"(a), "l"(b), "l"(c)); return d;
}
__device__ __forceinline__ u64 add2(u64 a, u64 b) {
    u64 d; asm("add.rn.f32x2 %0, %1, %2;" : "=l"(d) : "l"(a), "l"(b)); return d;
}
__device__ __forceinline__ u64 mul2(u64 a, u64 b) {
    u64 d; asm("mul.rn.f32x2 %0, %1, %2;" : "=l"(d) : "l"(a), "l"(b)); return d;
}
__device__ __forceinline__ uint32_t smem_u32(const void* p) {
    uint32_t a;
    asm("{ .reg .u64 t; cvta.to.shared.u64 t, %1; cvt.u32.u64 %0, t; }"
        : "=r"(a) : "l"(p));
    return a;
}
__device__ __forceinline__ float ftanh(float a) {
    float e = __expf(2.0f * a);
    return 1.0f - __fdividef(2.0f, e + 1.0f);
}
#define CP16(dst, src) \
    asm volatile("cp.async.cg.shared.global [%0], [%1], 16;" \
                 :: "r"(dst), "l"(src) : "memory")

// dynamic shared layout (float offsets)
#define F_W1T 0                       // [j][i] 128x32
#define F_W2S (F_W1T + HH * DD)       // W2 rows 0..63: [j][k] 64x32
#define F_NS  (F_W2S + (HH/2) * DD)   // noise staging: [chunk(8)][tid(256)][4]
#define SMEM_FLOATS (F_NS + TPB * DD)
#define SMEM_BYTES (SMEM_FLOATS * 4)

// layer-1 for hidden units (JJ, JJ+64): 16 fma2 + 2 add2, one LDS.64 for cs pair
#define LAYER1(JJ, CSP, P0, P1) do { \
    const ulonglong2* _w1a = (const ulonglong2*)(W1T + (JJ) * DD); \
    const ulonglong2* _w1b = (const ulonglong2*)(W1T + ((JJ) + 64) * DD); \
    u64 _q0 = zero2, _q1 = zero2, _q2 = zero2, _q3 = zero2; \
    _Pragma("unroll") \
    for (int _i = 0; _i < 8; _i++) { \
        ulonglong2 _wa = _w1a[_i]; \
        ulonglong2 _wb = _w1b[_i]; \
        _q0 = fma2(Xp[2*_i],   _wa.x, _q0); \
        _q1 = fma2(Xp[2*_i+1], _wa.y, _q1); \
        _q2 = fma2(Xp[2*_i],   _wb.x, _q2); \
        _q3 = fma2(Xp[2*_i+1], _wb.y, _q3); \
    } \
    _q0 = add2(_q0, _q1); \
    _q2 = add2(_q2, _q3); \
    const float2 _cs = (CSP)[JJ]; \
    float _tl, _th; \
    unpack2(_q0, _tl, _th); (P0) = _cs.x + (_tl + _th); \
    unpack2(_q2, _tl, _th); (P1) = _cs.y + (_tl + _th); \
} while (0)

// layer-2: unit JJ via SMEM (W2S), unit JJ+64 via CONST (W2c) — port-balanced
#define LAYER2(JJ, H0P, H1P) do { \
    const ulonglong2* _w2a = (const ulonglong2*)(W2S + (JJ) * DD); \
    const ulonglong2* _w2b = (const ulonglong2*)(W2c + ((JJ) + 64) * DD); \
    _Pragma("unroll") \
    for (int _i = 0; _i < 8; _i++) { \
        ulonglong2 _wa = _w2a[_i]; \
        ulonglong2 _wb = _w2b[_i]; \
        Zp[2*_i]   = fma2((H0P), _wa.x, Zp[2*_i]); \
        Zp[2*_i+1] = fma2((H0P), _wa.y, Zp[2*_i+1]); \
        Zp[2*_i]   = fma2((H1P), _wb.x, Zp[2*_i]); \
        Zp[2*_i+1] = fma2((H1P), _wb.y, Zp[2*_i+1]); \
    } \
} while (0)

__global__ __launch_bounds__(TPB, 1)
void sde_kernel(const float* __restrict__ obs,
                const float* __restrict__ X0,
                const float* __restrict__ V0,
                const float* __restrict__ noise,
                const float* __restrict__ W1,
                const float* __restrict__ b1,
                const float* __restrict__ W2,
                const float* __restrict__ b2,
                const float* __restrict__ theta_p,
                const int*   __restrict__ obsidx_p,
                const int*   __restrict__ cr_p,
                float* __restrict__ outX,
                float* __restrict__ outV)
{
    extern __shared__ __align__(16) float sm[];
    float* W1T = sm + F_W1T;
    float* W2S = sm + F_W2S;
    float* ns  = sm + F_NS;

    __shared__ float2 cb[HH];           // (base_j, w40_j)
    __shared__ float2 cspbuf[2][HH/2];  // per-step cs pairs, double-buffered
    __shared__ __align__(16) float b2s[DD];

    const int tid = threadIdx.x;

    // ---- stage W1^T, W2 lower half, folded constants ----
    for (int idx = tid; idx < DD * HH; idx += TPB) {
        int i = idx >> 7;            // feature
        int j = idx & (HH - 1);      // hidden unit
        W1T[j * DD + i] = W1[idx];
    }
    for (int idx = tid; idx < (HH/2) * DD; idx += TPB)
        W2S[idx] = W2[idx];          // rows 0..63, already [j][k]
    if (tid < DD) b2s[tid] = b2[tid];
    if (tid < HH) {
        const int j = tid;
        float base = b1[j];
        #pragma unroll
        for (int q = 0; q < PP; q++)
            base = fmaf(obs[q], W1[(DD + q) * HH + j], base);
        base = fmaf((float)(*obsidx_p), W1[41 * HH + j], base);
        cb[j] = make_float2(base, W1[40 * HH + j]);
    }

    const float theta = *theta_p;
    const float crf   = (float)(*cr_p);
    const float dt    = 0.02f;
    const float sqdt  = sqrtf(dt);

    const u64 sq2   = pack2(sqdt, sqdt);
    const u64 dt2   = pack2(dt, dt);
    const u64 nth2  = pack2(-theta, -theta);
    const u64 ncr2  = pack2(-crf, -crf);
    const u64 zero2 = pack2(0.f, 0.f);

    const int p = (int)blockIdx.x * TPB + tid;   // exactly NPART threads

    const uint32_t nsu = smem_u32(ns) + (uint32_t)tid * 16u;
    const float* nrd = ns + tid * 4;

    __syncthreads();

    // ---- state packed f32x2: X 16 u64, Z 16 u64 ----
    u64 Xp[DD/2], Zp[DD/2];
    {
        const ulonglong2* xr = (const ulonglong2*)(X0 + (size_t)p * DD);
        #pragma unroll
        for (int i = 0; i < DD/4; i++) {
            ulonglong2 v = xr[i];
            Xp[2*i] = v.x; Xp[2*i+1] = v.y;
        }
    }
    float V = V0[p];

    const u64* b2u = (const u64*)b2s;

    for (int m = 0; m < MS; m++) {
        const float s = (float)m * dt;
        const float2* csp = cspbuf[m & 1];

        // per-step cs pairs (one thread per jj), double-buffered
        if (tid < HH / 2) {
            float2 ca = cb[tid];
            float2 cbx = cb[tid + HH / 2];
            cspbuf[m & 1][tid] =
                make_float2(fmaf(s, ca.y, ca.x), fmaf(s, cbx.y, cbx.x));
        }

        // stage this step's noise row into shared (epilogue consumes)
        {
            const float* src = noise + ((size_t)m * NPART + p) * DD;
            #pragma unroll
            for (int i = 0; i < 8; i++)
                CP16(nsu + (uint32_t)i * (TPB * 16u), src + i * 4);
            asm volatile("cp.async.commit_group;" ::: "memory");
        }
        __syncthreads();   // csp ready (also orders double-buffer reuse)

        #pragma unroll
        for (int i = 0; i < DD/2; i++) Zp[i] = b2u[i];

        // ---- software-pipelined MLP: tanh(jj) hides under layer1(jj+1) ----
        float pre0, pre1;
        LAYER1(0, csp, pre0, pre1);
        #pragma unroll 2
        for (int jj = 0; jj < HH / 2 - 1; jj++) {
            const float h0 = ftanh(pre0);     // MUFU chain issued...
            const float h1 = ftanh(pre1);
            float npre0, npre1;
            LAYER1(jj + 1, csp, npre0, npre1); // ...overlapped with this
            const u64 h0p = pack2(h0, h0);
            const u64 h1p = pack2(h1, h1);
            LAYER2(jj, h0p, h1p);
            pre0 = npre0;
            pre1 = npre1;
        }
        {
            const float h0 = ftanh(pre0);
            const float h1 = ftanh(pre1);
            const u64 h0p = pack2(h0, h0);
            const u64 h1p = pack2(h1, h1);
            LAYER2(HH / 2 - 1, h0p, h1p);
        }

        // ---- epilogue (noise from shared) ----
        asm volatile("cp.async.wait_group 0;" ::: "memory");

        u64 s20 = zero2, s21 = zero2, s22 = zero2, s23 = zero2;
        u64 zw0 = zero2, zw1 = zero2, zw2 = zero2, zw3 = zero2;
        #pragma unroll
        for (int i = 0; i < 4; i++) {
            ulonglong2 nv0 = *(const ulonglong2*)(nrd + (2*i)     * (TPB * 4));
            ulonglong2 nv1 = *(const ulonglong2*)(nrd + (2*i + 1) * (TPB * 4));
            u64 za = Zp[4*i],     zb = Zp[4*i + 1];
            u64 zc = Zp[4*i + 2], zd = Zp[4*i + 3];
            s20 = fma2(za, za, s20);
            s21 = fma2(zb, zb, s21);
            s22 = fma2(zc, zc, s22);
            s23 = fma2(zd, zd, s23);
            u64 wa = mul2(sq2, nv0.x);
            u64 wb = mul2(sq2, nv0.y);
            u64 wc = mul2(sq2, nv1.x);
            u64 wd = mul2(sq2, nv1.y);
            zw0 = fma2(za, wa, zw0);
            zw1 = fma2(zb, wb, zw1);
            zw2 = fma2(zc, wc, zw2);
            zw3 = fma2(zd, wd, zw3);
            u64 d0 = fma2(ncr2, za, mul2(nth2, Xp[4*i]));
            u64 d1 = fma2(ncr2, zb, mul2(nth2, Xp[4*i + 1]));
            u64 d2 = fma2(ncr2, zc, mul2(nth2, Xp[4*i + 2]));
            u64 d3 = fma2(ncr2, zd, mul2(nth2, Xp[4*i + 3]));
            Xp[4*i]     = add2(fma2(dt2, d0, Xp[4*i]),     wa);
            Xp[4*i + 1] = add2(fma2(dt2, d1, Xp[4*i + 1]), wb);
            Xp[4*i + 2] = add2(fma2(dt2, d2, Xp[4*i + 2]), wc);
            Xp[4*i + 3] = add2(fma2(dt2, d3, Xp[4*i + 3]), wd);
        }
        s20 = add2(add2(s20, s21), add2(s22, s23));
        zw0 = add2(add2(zw0, zw1), add2(zw2, zw3));
        float qlo, qhi, wlo, whi;
        unpack2(s20, qlo, qhi);
        unpack2(zw0, wlo, whi);
        V = fmaf(dt * (0.5f - crf), qlo + qhi, V) + (wlo + whi);
    }

    // ---- store ----
    {
        ulonglong2* xo = (ulonglong2*)(outX + (size_t)p * DD);
        #pragma unroll
        for (int i = 0; i < DD/4; i++) {
            ulonglong2 v; v.x = Xp[2*i]; v.y = Xp[2*i+1];
            xo[i] = v;
        }
        outV[p] = V;
    }
}

extern "C" void kernel_launch(void* const* d_in, const int* in_sizes, int n_in,
                              void* d_out, int out_size) {
    const float* obs    = (const float*)d_in[0];
    const float* X0     = (const float*)d_in[1];
    const float* V0     = (const float*)d_in[2];
    const float* noise  = (const float*)d_in[3];
    const float* W1     = (const float*)d_in[4];
    const float* b1     = (const float*)d_in[5];
    const float* W2     = (const float*)d_in[6];
    const float* b2     = (const float*)d_in[7];
    const float* theta  = (const float*)d_in[8];
    const int*   obsidx = (const int*)d_in[9];
    const int*   cr     = (const int*)d_in[10];

    float* out  = (float*)d_out;
    float* outX = out;
    float* outV = out + (size_t)NPART * DD;

    // Stage W2 into constant memory (D2D async copy: graph-capturable, no alloc)
    cudaMemcpyToSymbolAsync(W2c, W2, HH * DD * sizeof(float), 0,
                            cudaMemcpyDeviceToDevice, 0);

    cudaFuncSetAttribute(sde_kernel,
                         cudaFuncAttributeMaxDynamicSharedMemorySize, SMEM_BYTES);
    sde_kernel<<<NBLK, TPB, SMEM_BYTES>>>(obs, X0, V0, noise, W1, b1, W2, b2,
                                          theta, obsidx, cr, outX, outV);
}